// round 15
// baseline (speedup 1.0000x reference)
#include <cuda_runtime.h>
#include <cuda_bf16.h>
#include <cuda_fp16.h>
#include <math.h>
#include <stdint.h>

// ---------------------------------------------------------------------------
// stGCL GAT autoencoder.
//  - Feature GEMMs + decode projections: single-term fp16 mma.sync, 3-stage
//    cp.async pipeline.
//  - W2 GEMMs (h2-critical, tiny): bf16 hi/lo 3-term, fp32 accum.
//  - Attention: CSR gather softmax+aggregation, fused ELU+convert, MLP-4
//    unrolled aggregation loop.
//  - Perm-path logits via gather identity (no extra dots launches).
// NOTE: tcgen05 unusable — harness compiles for plain sm_103 target.
// ---------------------------------------------------------------------------

#define MAXN 30016
#define MAXE 480000
#define MAXAK 3000

typedef __nv_bfloat16 bf16;

__device__ bf16  g_Ah[(size_t)MAXN * MAXAK];   // also aliased as __half buffer
__device__ bf16  g_Al[(size_t)MAXN * 512];
__device__ float g_Hx[MAXN * 256];
__device__ float g_Hr[MAXN * 256];
__device__ float g_A [MAXN * 512];
__device__ float g_es[MAXN];
__device__ float g_ed[MAXN];
__device__ float g_esx[MAXN];
__device__ float g_edx[MAXN];
__device__ float g_esr[MAXN];
__device__ float g_edr[MAXN];
__device__ int g_roff[MAXN + 1];
__device__ int g_cnt [MAXN];
__device__ int g_cur [MAXN];
__device__ int g_rsrc[MAXE];
// weights
__device__ __half g_W1xT_f16[256 * 3000];   // [NH][INX]
__device__ __half g_W1rT_f16[256 * 2048];   // [NH][INR]
__device__ __half g_W1x_f16 [3000 * 256];   // [INX][NH]
__device__ __half g_W1r_f16 [2048 * 256];   // [INR][NH]
__device__ bf16 g_W2T_h [64 * 512];    __device__ bf16 g_W2T_l [64 * 512];
__device__ bf16 g_W2_h  [512 * 64];    __device__ bf16 g_W2_l  [512 * 64];

// ---------------------------------------------------------------------------
// helpers
// ---------------------------------------------------------------------------
__device__ __forceinline__ uint32_t s2u(const void* p)
{
    return (uint32_t)__cvta_generic_to_shared(p);
}

__device__ __forceinline__ void cpasync16(uint32_t saddr, const void* gaddr, bool pred)
{
    int sz = pred ? 16 : 0;
    asm volatile("cp.async.cg.shared.global [%0], [%1], 16, %2;\n"
                 :: "r"(saddr), "l"(gaddr), "r"(sz));
}

__device__ __forceinline__ void ldmatrix_x4(uint32_t* r, uint32_t saddr)
{
    asm volatile("ldmatrix.sync.aligned.m8n8.x4.shared.b16 {%0,%1,%2,%3}, [%4];"
                 : "=r"(r[0]), "=r"(r[1]), "=r"(r[2]), "=r"(r[3]) : "r"(saddr));
}

__device__ __forceinline__ void ldmatrix_x2(uint32_t* r, uint32_t saddr)
{
    asm volatile("ldmatrix.sync.aligned.m8n8.x2.shared.b16 {%0,%1}, [%2];"
                 : "=r"(r[0]), "=r"(r[1]) : "r"(saddr));
}

__device__ __forceinline__ void mma16816_bf(float* c, const uint32_t* a, const uint32_t* b)
{
    asm volatile("mma.sync.aligned.m16n8k16.row.col.f32.bf16.bf16.f32 "
                 "{%0,%1,%2,%3}, {%4,%5,%6,%7}, {%8,%9}, {%0,%1,%2,%3};"
                 : "+f"(c[0]), "+f"(c[1]), "+f"(c[2]), "+f"(c[3])
                 : "r"(a[0]), "r"(a[1]), "r"(a[2]), "r"(a[3]), "r"(b[0]), "r"(b[1]));
}

__device__ __forceinline__ void mma16816_f16(float* c, const uint32_t* a, const uint32_t* b)
{
    asm volatile("mma.sync.aligned.m16n8k16.row.col.f32.f16.f16.f32 "
                 "{%0,%1,%2,%3}, {%4,%5,%6,%7}, {%8,%9}, {%0,%1,%2,%3};"
                 : "+f"(c[0]), "+f"(c[1]), "+f"(c[2]), "+f"(c[3])
                 : "r"(a[0]), "r"(a[1]), "r"(a[2]), "r"(a[3]), "r"(b[0]), "r"(b[1]));
}

// ---------------------------------------------------------------------------
// conversion kernels
// ---------------------------------------------------------------------------
__global__ void split_kernel(const float* __restrict__ x,
                             bf16* __restrict__ hi, bf16* __restrict__ lo,
                             size_t n)
{
    size_t i = (size_t)blockIdx.x * blockDim.x + threadIdx.x;
    if (i >= n) return;
    float v = x[i];
    bf16 h = __float2bfloat16(v);
    hi[i] = h;
    lo[i] = __float2bfloat16(v - __bfloat162float(h));
}

__global__ void tsplit_kernel(const float* __restrict__ x, int R, int C,
                              bf16* __restrict__ hi, bf16* __restrict__ lo)
{
    int i = blockIdx.x * blockDim.x + threadIdx.x;
    if (i >= R * C) return;
    int c = i / R;
    int r = i - c * R;
    float v = x[(size_t)r * C + c];
    bf16 h = __float2bfloat16(v);
    hi[i] = h;
    lo[i] = __float2bfloat16(v - __bfloat162float(h));
}

__global__ void cvt_f16_kernel(const float* __restrict__ x,
                               __half* __restrict__ y, size_t n)
{
    size_t i = (size_t)blockIdx.x * blockDim.x + threadIdx.x;
    if (i < n) y[i] = __float2half(x[i]);
}

// transpose + fp16: out[c][r] = fp16(x[r][c]), out dims [C][R]
__global__ void tcvt_f16_kernel(const float* __restrict__ x, int R, int C,
                                __half* __restrict__ y)
{
    int i = blockIdx.x * blockDim.x + threadIdx.x;
    if (i >= R * C) return;
    int c = i / R;
    int r = i - c * R;
    y[i] = __float2half(x[(size_t)r * C + c]);
}

// ===========================================================================
// 3-term bf16 split GEMM (proven): C[M,N] = (Ah+Al)[M,K]*(Bh+Bl)[N,K]^T
// ===========================================================================
#define BM 128
#define BN 128
#define BKT 32
#define SROW 40
#define TILE_E (BM * SROW)
#define SMEM_BYTES (4 * 2 * TILE_E * 2)

__global__ __launch_bounds__(256) void gemm_mma_kernel(
    const bf16* __restrict__ Ah, const bf16* __restrict__ Al, int lda,
    const bf16* __restrict__ Bh, const bf16* __restrict__ Bl, int ldb,
    float* __restrict__ C, int ldc, int M, int N, int K)
{
    extern __shared__ bf16 smem[];
    const int tid  = threadIdx.x;
    const int lane = tid & 31;
    const int wid  = tid >> 5;
    const int wm   = wid & 1;
    const int wn   = wid >> 1;
    const int bm   = blockIdx.y * BM;
    const int bn   = blockIdx.x * BN;

    bf16* sA[2][2]; bf16* sB[2][2];
    #pragma unroll
    for (int st = 0; st < 2; st++) {
        bf16* base = smem + st * 4 * TILE_E;
        sA[st][0] = base;
        sA[st][1] = base + TILE_E;
        sB[st][0] = base + 2 * TILE_E;
        sB[st][1] = base + 3 * TILE_E;
    }

    float acc[4][4][4];
    #pragma unroll
    for (int i = 0; i < 4; i++)
        #pragma unroll
        for (int j = 0; j < 4; j++)
            #pragma unroll
            for (int k = 0; k < 4; k++) acc[i][j][k] = 0.f;

    const int KT = (K + BKT - 1) / BKT;

    auto load_stage = [&](int st, int k0) {
        #pragma unroll
        for (int j = 0; j < 2; j++) {
            int chunk = tid + j * 256;
            int row = chunk >> 2;
            int cc  = chunk & 3;
            int gk  = k0 + cc * 8;
            {
                int gr = bm + row;
                bool p = (gr < M) && (gk < K);
                size_t off = (size_t)(p ? gr : 0) * lda + (p ? gk : 0);
                cpasync16(s2u(sA[st][0] + row * SROW + cc * 8), Ah + off, p);
                cpasync16(s2u(sA[st][1] + row * SROW + cc * 8), Al + off, p);
            }
            {
                int gr = bn + row;
                bool p = (gr < N) && (gk < K);
                size_t off = (size_t)(p ? gr : 0) * ldb + (p ? gk : 0);
                cpasync16(s2u(sB[st][0] + row * SROW + cc * 8), Bh + off, p);
                cpasync16(s2u(sB[st][1] + row * SROW + cc * 8), Bl + off, p);
            }
        }
    };

    load_stage(0, 0);
    asm volatile("cp.async.commit_group;\n");

    for (int kt = 0; kt < KT; kt++) {
        if (kt + 1 < KT) {
            load_stage((kt + 1) & 1, (kt + 1) * BKT);
            asm volatile("cp.async.commit_group;\n");
            asm volatile("cp.async.wait_group 1;\n");
        } else {
            asm volatile("cp.async.wait_group 0;\n");
        }
        __syncthreads();

        int st = kt & 1;
        #pragma unroll
        for (int kk = 0; kk < BKT; kk += 16) {
            uint32_t ah[4][4], al[4][4];
            int arow = wm * 64 + (lane & 15);
            int acol = kk + (lane >> 4) * 8;
            #pragma unroll
            for (int mi = 0; mi < 4; mi++) {
                ldmatrix_x4(ah[mi], s2u(sA[st][0] + (arow + mi * 16) * SROW + acol));
                ldmatrix_x4(al[mi], s2u(sA[st][1] + (arow + mi * 16) * SROW + acol));
            }
            int brow = wn * 32 + (lane & 7);
            int bcol = kk + ((lane >> 3) & 1) * 8;
            uint32_t bb[4][2];
            #pragma unroll
            for (int ni = 0; ni < 4; ni++)
                ldmatrix_x2(bb[ni], s2u(sB[st][0] + (brow + ni * 8) * SROW + bcol));
            #pragma unroll
            for (int mi = 0; mi < 4; mi++)
                #pragma unroll
                for (int ni = 0; ni < 4; ni++) {
                    mma16816_bf(acc[mi][ni], ah[mi], bb[ni]);
                    mma16816_bf(acc[mi][ni], al[mi], bb[ni]);
                }
            #pragma unroll
            for (int ni = 0; ni < 4; ni++)
                ldmatrix_x2(bb[ni], s2u(sB[st][1] + (brow + ni * 8) * SROW + bcol));
            #pragma unroll
            for (int mi = 0; mi < 4; mi++)
                #pragma unroll
                for (int ni = 0; ni < 4; ni++)
                    mma16816_bf(acc[mi][ni], ah[mi], bb[ni]);
        }
        __syncthreads();
    }

    const int group = lane >> 2;
    const int tig   = lane & 3;
    #pragma unroll
    for (int mi = 0; mi < 4; mi++) {
        #pragma unroll
        for (int ni = 0; ni < 4; ni++) {
            int col = bn + wn * 32 + ni * 8 + tig * 2;
            if (col >= N) continue;
            int r0 = bm + wm * 64 + mi * 16 + group;
            if (r0 < M) {
                float2 v = make_float2(acc[mi][ni][0], acc[mi][ni][1]);
                *(float2*)&C[(size_t)r0 * ldc + col] = v;
            }
            int r1 = r0 + 8;
            if (r1 < M) {
                float2 v = make_float2(acc[mi][ni][2], acc[mi][ni][3]);
                *(float2*)&C[(size_t)r1 * ldc + col] = v;
            }
        }
    }
}

// ===========================================================================
// single-term fp16 GEMM, 3-stage cp.async pipeline: C[M,N] = A[M,K]*B[N,K]^T
// ===========================================================================
#define SMEM_F16 (3 * 2 * TILE_E * 2)   // 3 stages, 2 matrices -> 61440 B

__global__ __launch_bounds__(256) void gemm_f16_kernel(
    const __half* __restrict__ A, int lda,
    const __half* __restrict__ B, int ldb,
    float* __restrict__ C, int ldc, int M, int N, int K)
{
    extern __shared__ __half smh[];
    const int tid  = threadIdx.x;
    const int lane = tid & 31;
    const int wid  = tid >> 5;
    const int wm   = wid & 1;
    const int wn   = wid >> 1;
    const int bm   = blockIdx.y * BM;
    const int bn   = blockIdx.x * BN;

    __half* sA[3]; __half* sB[3];
    #pragma unroll
    for (int st = 0; st < 3; st++) {
        __half* base = smh + st * 2 * TILE_E;
        sA[st] = base;
        sB[st] = base + TILE_E;
    }

    float acc[4][4][4];
    #pragma unroll
    for (int i = 0; i < 4; i++)
        #pragma unroll
        for (int j = 0; j < 4; j++)
            #pragma unroll
            for (int k = 0; k < 4; k++) acc[i][j][k] = 0.f;

    const int KT = (K + BKT - 1) / BKT;

    auto load_stage = [&](int st, int k0) {
        #pragma unroll
        for (int j = 0; j < 2; j++) {
            int chunk = tid + j * 256;
            int row = chunk >> 2;
            int cc  = chunk & 3;
            int gk  = k0 + cc * 8;
            {
                int gr = bm + row;
                bool p = (gr < M) && (gk < K);
                size_t off = (size_t)(p ? gr : 0) * lda + (p ? gk : 0);
                cpasync16(s2u(sA[st] + row * SROW + cc * 8), A + off, p);
            }
            {
                int gr = bn + row;
                bool p = (gr < N) && (gk < K);
                size_t off = (size_t)(p ? gr : 0) * ldb + (p ? gk : 0);
                cpasync16(s2u(sB[st] + row * SROW + cc * 8), B + off, p);
            }
        }
    };

    // prologue: 2 stages in flight (zfill preds make over-issue safe)
    load_stage(0, 0);
    asm volatile("cp.async.commit_group;\n");
    load_stage(1, BKT);
    asm volatile("cp.async.commit_group;\n");

    for (int kt = 0; kt < KT; kt++) {
        asm volatile("cp.async.wait_group 1;\n");   // stage kt ready
        __syncthreads();

        int st = kt % 3;
        #pragma unroll
        for (int kk = 0; kk < BKT; kk += 16) {
            uint32_t af[4][4];
            int arow = wm * 64 + (lane & 15);
            int acol = kk + (lane >> 4) * 8;
            #pragma unroll
            for (int mi = 0; mi < 4; mi++)
                ldmatrix_x4(af[mi], s2u(sA[st] + (arow + mi * 16) * SROW + acol));
            int brow = wn * 32 + (lane & 7);
            int bcol = kk + ((lane >> 3) & 1) * 8;
            uint32_t bb[4][2];
            #pragma unroll
            for (int ni = 0; ni < 4; ni++)
                ldmatrix_x2(bb[ni], s2u(sB[st] + (brow + ni * 8) * SROW + bcol));
            #pragma unroll
            for (int mi = 0; mi < 4; mi++)
                #pragma unroll
                for (int ni = 0; ni < 4; ni++)
                    mma16816_f16(acc[mi][ni], af[mi], bb[ni]);
        }
        __syncthreads();

        if (kt + 2 < KT)
            load_stage((kt + 2) % 3, (kt + 2) * BKT);
        asm volatile("cp.async.commit_group;\n");   // commit (possibly empty)
    }

    const int group = lane >> 2;
    const int tig   = lane & 3;
    #pragma unroll
    for (int mi = 0; mi < 4; mi++) {
        #pragma unroll
        for (int ni = 0; ni < 4; ni++) {
            int col = bn + wn * 32 + ni * 8 + tig * 2;
            if (col >= N) continue;
            int r0 = bm + wm * 64 + mi * 16 + group;
            if (r0 < M) {
                float2 v = make_float2(acc[mi][ni][0], acc[mi][ni][1]);
                *(float2*)&C[(size_t)r0 * ldc + col] = v;
            }
            int r1 = r0 + 8;
            if (r1 < M) {
                float2 v = make_float2(acc[mi][ni][2], acc[mi][ni][3]);
                *(float2*)&C[(size_t)r1 * ldc + col] = v;
            }
        }
    }
}

// ---------------------------------------------------------------------------
// CSR build
// ---------------------------------------------------------------------------
__global__ void zero_cnt_kernel(int* cnt, int N)
{
    int i = blockIdx.x * blockDim.x + threadIdx.x;
    if (i < N) cnt[i] = 0;
}

__global__ void count_kernel(const int* __restrict__ dst, int* cnt, int E)
{
    int i = blockIdx.x * blockDim.x + threadIdx.x;
    if (i < E) atomicAdd(&cnt[dst[i]], 1);
}

__global__ void scan_kernel(const int* __restrict__ cnt,
                            int* __restrict__ roff, int* __restrict__ cur, int N)
{
    __shared__ int ssum[1024];
    int t = threadIdx.x;
    int per = (N + 1023) / 1024;
    int b = t * per;
    int loc = 0;
    for (int i = 0; i < per; i++)
        if (b + i < N) loc += cnt[b + i];
    ssum[t] = loc;
    __syncthreads();
    for (int o = 1; o < 1024; o <<= 1) {
        int v = (t >= o) ? ssum[t - o] : 0;
        __syncthreads();
        ssum[t] += v;
        __syncthreads();
    }
    int run = (t == 0) ? 0 : ssum[t - 1];
    for (int i = 0; i < per; i++) {
        if (b + i < N) {
            roff[b + i] = run;
            cur[b + i]  = run;
            run += cnt[b + i];
        }
    }
    if (t == 1023) roff[N] = ssum[1023];
}

__global__ void fill_kernel(const int* __restrict__ src,
                            const int* __restrict__ dst,
                            int* __restrict__ cur, int* __restrict__ rsrc, int E)
{
    int i = blockIdx.x * blockDim.x + threadIdx.x;
    if (i >= E) return;
    int pos = atomicAdd(&cur[dst[i]], 1);
    rsrc[pos] = src[i];
}

// ---------------------------------------------------------------------------
// Attention
// ---------------------------------------------------------------------------
__global__ void dots_kernel(const float* __restrict__ H, int ld, int D,
                            const float* __restrict__ asrc,
                            const float* __restrict__ adst,
                            float* __restrict__ es, float* __restrict__ ed, int N)
{
    int warp = (blockIdx.x * blockDim.x + threadIdx.x) >> 5;
    int lane = threadIdx.x & 31;
    if (warp >= N) return;
    const float* h = H + (size_t)warp * ld;
    float s1 = 0.f, s2 = 0.f;
    for (int d = lane; d < D; d += 32) {
        float v = h[d];
        s1 += v * asrc[d];
        s2 += v * adst[d];
    }
    #pragma unroll
    for (int o = 16; o; o >>= 1) {
        s1 += __shfl_xor_sync(0xffffffffu, s1, o);
        s2 += __shfl_xor_sync(0xffffffffu, s2, o);
    }
    if (lane == 0) { es[warp] = s1; ed[warp] = s2; }
}

// Fused per-node softmax + aggregation + ELU + output convert.
// Phase-B aggregation unrolled x4 with independent partial accumulators
// (MLP=4 on the L2-resident H-row gathers).
// OMODE: 0 = bf16 hi/lo split pair, 1 = single fp16.
#define ACHUNK 64
template <int NCH, int OMODE>
__global__ __launch_bounds__(256) void csr_attn_kernel(
    const float* __restrict__ H, int ldh,
    const int* __restrict__ p,
    const float* __restrict__ es, const float* __restrict__ ed,
    const int* __restrict__ roff, const int* __restrict__ rsrc,
    bf16* __restrict__ outh, bf16* __restrict__ outl,
    int ldo, int coloff)
{
    const int node = blockIdx.x;
    const int tid  = threadIdx.x;
    const int lane = tid & 31;
    const int wid  = tid >> 5;
    const int beg = roff[node];
    const int deg = roff[node + 1] - beg;

    __shared__ float s_w[ACHUNK];
    __shared__ int   s_src[ACHUNK];
    __shared__ float s_ms[2];

    const float edv = ed[p ? p[node] : node];

    if (wid == 0) {
        float m = -INFINITY;
        for (int j = lane; j < deg; j += 32) {
            int sidx = rsrc[beg + j];
            float e = es[p ? p[sidx] : sidx] + edv;
            e = (e >= 0.f) ? e : 0.2f * e;
            m = fmaxf(m, e);
        }
        #pragma unroll
        for (int o = 16; o; o >>= 1) m = fmaxf(m, __shfl_xor_sync(0xffffffffu, m, o));
        float ssum = 0.f;
        for (int j = lane; j < deg; j += 32) {
            int sidx = rsrc[beg + j];
            float e = es[p ? p[sidx] : sidx] + edv;
            e = (e >= 0.f) ? e : 0.2f * e;
            ssum += __expf(e - m);
        }
        #pragma unroll
        for (int o = 16; o; o >>= 1) ssum += __shfl_xor_sync(0xffffffffu, ssum, o);
        if (lane == 0) { s_ms[0] = m; s_ms[1] = ssum; }
    }
    __syncthreads();
    const float m    = s_ms[0];
    const float invs = 1.f / (s_ms[1] + 1e-16f);

    float acc0 = 0.f, acc1 = 0.f;
    for (int c0 = 0; c0 < deg; c0 += ACHUNK) {
        int cl = min(ACHUNK, deg - c0);
        if (tid < cl) {
            int sidx = rsrc[beg + c0 + tid];
            int ps = p ? p[sidx] : sidx;
            float e = es[ps] + edv;
            e = (e >= 0.f) ? e : 0.2f * e;
            s_w[tid]   = __expf(e - m) * invs;
            s_src[tid] = ps;
        }
        __syncthreads();

        float a0 = 0.f, a1 = 0.f, a2 = 0.f, a3 = 0.f;
        float b0 = 0.f, b1 = 0.f, b2 = 0.f, b3 = 0.f;
        int j = 0;
        for (; j + 4 <= cl; j += 4) {
            const float* r0 = H + (size_t)s_src[j + 0] * ldh;
            const float* r1 = H + (size_t)s_src[j + 1] * ldh;
            const float* r2 = H + (size_t)s_src[j + 2] * ldh;
            const float* r3 = H + (size_t)s_src[j + 3] * ldh;
            float w0 = s_w[j + 0], w1 = s_w[j + 1];
            float w2 = s_w[j + 2], w3 = s_w[j + 3];
            a0 += w0 * r0[tid];
            a1 += w1 * r1[tid];
            a2 += w2 * r2[tid];
            a3 += w3 * r3[tid];
            if (NCH == 2) {
                b0 += w0 * r0[tid + 256];
                b1 += w1 * r1[tid + 256];
                b2 += w2 * r2[tid + 256];
                b3 += w3 * r3[tid + 256];
            }
        }
        for (; j < cl; j++) {
            const float* r = H + (size_t)s_src[j] * ldh;
            float w = s_w[j];
            a0 += w * r[tid];
            if (NCH == 2) b0 += w * r[tid + 256];
        }
        acc0 += (a0 + a1) + (a2 + a3);
        if (NCH == 2) acc1 += (b0 + b1) + (b2 + b3);
        __syncthreads();
    }

    acc0 = (acc0 > 0.f) ? acc0 : expm1f(acc0);
    if (NCH == 2) acc1 = (acc1 > 0.f) ? acc1 : expm1f(acc1);

    size_t base = (size_t)node * ldo + coloff;
    if (OMODE == 0) {
        bf16 h0 = __float2bfloat16(acc0);
        outh[base + tid] = h0;
        outl[base + tid] = __float2bfloat16(acc0 - __bfloat162float(h0));
        if (NCH == 2) {
            bf16 h1 = __float2bfloat16(acc1);
            outh[base + tid + 256] = h1;
            outl[base + tid + 256] = __float2bfloat16(acc1 - __bfloat162float(h1));
        }
    } else {
        __half* oh = (__half*)outh;
        oh[base + tid] = __float2half(acc0);
        if (NCH == 2) oh[base + tid + 256] = __float2half(acc1);
    }
}

__global__ void summary_kernel(const float* __restrict__ h2, int N, int C,
                               float* __restrict__ out)
{
    int c = blockIdx.x;
    float acc = 0.f;
    for (int r = threadIdx.x; r < N; r += blockDim.x)
        acc += h2[(size_t)r * C + c];
    __shared__ float sh[256];
    sh[threadIdx.x] = acc;
    __syncthreads();
    for (int o = 128; o; o >>= 1) {
        if (threadIdx.x < o) sh[threadIdx.x] += sh[threadIdx.x + o];
        __syncthreads();
    }
    if (threadIdx.x == 0)
        out[c] = 1.f / (1.f + expf(-sh[0] / (float)N));
}

// ---------------------------------------------------------------------------
// Host side
// ---------------------------------------------------------------------------
static void gemm_mma(const bf16* Ah, const bf16* Al, int lda,
                     const bf16* Bh, const bf16* Bl, int ldb,
                     float* C, int ldc, int M, int N, int K)
{
    dim3 grid((N + BN - 1) / BN, (M + BM - 1) / BM);
    gemm_mma_kernel<<<grid, 256, SMEM_BYTES>>>(Ah, Al, lda, Bh, Bl, ldb,
                                               C, ldc, M, N, K);
}

static void gemm_f16(const __half* A, int lda, const __half* B, int ldb,
                     float* C, int ldc, int M, int N, int K)
{
    dim3 grid((N + BN - 1) / BN, (M + BM - 1) / BM);
    gemm_f16_kernel<<<grid, 256, SMEM_F16>>>(A, lda, B, ldb, C, ldc, M, N, K);
}

static void split(const float* x, bf16* hi, bf16* lo, size_t n)
{
    split_kernel<<<(unsigned)((n + 255) / 256), 256>>>(x, hi, lo, n);
}

extern "C" void kernel_launch(void* const* d_in, const int* in_sizes, int n_in,
                              void* d_out, int out_size)
{
    const float* features = (const float*)d_in[0];
    const float* imf      = (const float*)d_in[1];
    const float* W1x      = (const float*)d_in[2];
    const float* a1x_src  = (const float*)d_in[3];
    const float* a1x_dst  = (const float*)d_in[4];
    const float* W1r      = (const float*)d_in[5];
    const float* a1r_src  = (const float*)d_in[6];
    const float* a1r_dst  = (const float*)d_in[7];
    const float* W2       = (const float*)d_in[8];
    const float* a3_src   = (const float*)d_in[9];
    const float* a3_dst   = (const float*)d_in[10];
    const int*   edge     = (const int*)d_in[11];
    const int*   perm     = (const int*)d_in[12];

    const int NH  = in_sizes[3];              // 256
    const int INX = in_sizes[2] / NH;         // 3000
    const int INR = in_sizes[5] / NH;         // 2048
    const int OUT = in_sizes[8] / (2 * NH);   // 64
    const int N   = in_sizes[0] / INX;        // 30000
    const int E   = in_sizes[11] / 2;         // 480000
    const int D2  = 2 * NH;                   // 512

    const int* src = edge;
    const int* dst = edge + E;

    cudaFuncSetAttribute(gemm_mma_kernel,
                         cudaFuncAttributeMaxDynamicSharedMemorySize, SMEM_BYTES);
    cudaFuncSetAttribute(gemm_f16_kernel,
                         cudaFuncAttributeMaxDynamicSharedMemorySize, SMEM_F16);

    bf16 *Ah, *Al;
    __half *W1xT_f16, *W1rT_f16, *W1x_f16, *W1r_f16;
    bf16 *W2T_h, *W2T_l, *W2_h, *W2_l;
    float *Hx, *Hr, *Abuf, *es, *ed, *esx, *edx, *esr, *edr;
    int *roff, *cnt, *cur, *rsrc;
    cudaGetSymbolAddress((void**)&Ah,   g_Ah);
    cudaGetSymbolAddress((void**)&Al,   g_Al);
    cudaGetSymbolAddress((void**)&Hx,   g_Hx);
    cudaGetSymbolAddress((void**)&Hr,   g_Hr);
    cudaGetSymbolAddress((void**)&Abuf, g_A);
    cudaGetSymbolAddress((void**)&es,   g_es);
    cudaGetSymbolAddress((void**)&ed,   g_ed);
    cudaGetSymbolAddress((void**)&esx,  g_esx);
    cudaGetSymbolAddress((void**)&edx,  g_edx);
    cudaGetSymbolAddress((void**)&esr,  g_esr);
    cudaGetSymbolAddress((void**)&edr,  g_edr);
    cudaGetSymbolAddress((void**)&roff, g_roff);
    cudaGetSymbolAddress((void**)&cnt,  g_cnt);
    cudaGetSymbolAddress((void**)&cur,  g_cur);
    cudaGetSymbolAddress((void**)&rsrc, g_rsrc);
    cudaGetSymbolAddress((void**)&W1xT_f16, g_W1xT_f16);
    cudaGetSymbolAddress((void**)&W1rT_f16, g_W1rT_f16);
    cudaGetSymbolAddress((void**)&W1x_f16,  g_W1x_f16);
    cudaGetSymbolAddress((void**)&W1r_f16,  g_W1r_f16);
    cudaGetSymbolAddress((void**)&W2T_h,  g_W2T_h);
    cudaGetSymbolAddress((void**)&W2T_l,  g_W2T_l);
    cudaGetSymbolAddress((void**)&W2_h,   g_W2_h);
    cudaGetSymbolAddress((void**)&W2_l,   g_W2_l);

    float* out = (float*)d_out;
    float* o_h2   = out;
    float* o_h4x  = o_h2   + (size_t)N * OUT;
    float* o_h4r  = o_h4x  + (size_t)N * INX;
    float* o_rh2  = o_h4r  + (size_t)N * INR;
    float* o_rh4x = o_rh2  + (size_t)N * OUT;
    float* o_rh4r = o_rh4x + (size_t)N * INX;
    float* o_sum  = o_rh4r + (size_t)N * INR;

    // ---- CSR build ----
    zero_cnt_kernel<<<(N + 255) / 256, 256>>>(cnt, N);
    count_kernel<<<(E + 255) / 256, 256>>>(dst, cnt, E);
    scan_kernel<<<1, 1024>>>(cnt, roff, cur, N);
    fill_kernel<<<(E + 255) / 256, 256>>>(src, dst, cur, rsrc, E);

    // ---- weight preps ----
    tcvt_f16_kernel<<<(INX * NH + 255) / 256, 256>>>(W1x, INX, NH, W1xT_f16);
    tcvt_f16_kernel<<<(INR * NH + 255) / 256, 256>>>(W1r, INR, NH, W1rT_f16);
    tsplit_kernel<<<(D2 * OUT + 255) / 256, 256>>>(W2, D2, OUT, W2T_h, W2T_l);
    split(W2, W2_h, W2_l, (size_t)D2 * OUT);
    cvt_f16_kernel<<<(INX * NH + 255) / 256, 256>>>(W1x, W1x_f16, (size_t)INX * NH);
    cvt_f16_kernel<<<(INR * NH + 255) / 256, 256>>>(W1r, W1r_f16, (size_t)INR * NH);

    // ---- shared pre-attention features: fp16 single-term GEMM ----
    __half* Af16 = (__half*)Ah;
    cvt_f16_kernel<<<(unsigned)(((size_t)N * INX + 255) / 256), 256>>>(
        features, Af16, (size_t)N * INX);
    gemm_f16(Af16, INX, W1xT_f16, INX, Hx, NH, N, NH, INX);
    cvt_f16_kernel<<<(unsigned)(((size_t)N * INR + 255) / 256), 256>>>(
        imf, Af16, (size_t)N * INR);
    gemm_f16(Af16, INR, W1rT_f16, INR, Hr, NH, N, NH, INR);

    // ---- encode dots once (perm path uses gather identity) ----
    dots_kernel<<<(N + 7) / 8, 256>>>(Hx, NH, NH, a1x_src, a1x_dst, esx, edx, N);
    dots_kernel<<<(N + 7) / 8, 256>>>(Hr, NH, NH, a1r_src, a1r_dst, esr, edr, N);

    for (int path = 0; path < 2; path++) {
        const int* p = path ? perm : nullptr;
        float* oh2  = path ? o_rh2  : o_h2;
        float* oh4x = path ? o_rh4x : o_h4x;
        float* oh4r = path ? o_rh4r : o_h4r;

        // --- encode: GAT layers (bf16 split out) -> @W2 (3-term) ---
        csr_attn_kernel<1, 0><<<N, 256>>>(Hx, NH, p, esx, edx, roff, rsrc,
                                          Ah, Al, D2, 0);
        csr_attn_kernel<1, 0><<<N, 256>>>(Hr, NH, p, esr, edr, roff, rsrc,
                                          Ah, Al, D2, NH);
        gemm_mma(Ah, Al, D2, W2T_h, W2T_l, D2, oh2, OUT, N, OUT, D2);

        // --- decode: hd = h2 @ W2^T (3-term), GAT (fp16 out), project (fp16) ---
        split(oh2, Ah, Al, (size_t)N * OUT);
        gemm_mma(Ah, Al, OUT, W2_h, W2_l, OUT, Abuf, D2, N, D2, OUT);

        dots_kernel<<<(N + 7) / 8, 256>>>(Abuf, D2, D2, a3_src, a3_dst, es, ed, N);
        csr_attn_kernel<2, 1><<<N, 256>>>(Abuf, D2, nullptr, es, ed, roff, rsrc,
                                          Ah, nullptr, D2, 0);

        const __half* H3 = (const __half*)Ah;
        gemm_f16(H3,      D2, W1x_f16, NH, oh4x, INX, N, INX, NH);
        gemm_f16(H3 + NH, D2, W1r_f16, NH, oh4r, INR, N, INR, NH);
    }

    summary_kernel<<<OUT, 256>>>(o_h2, N, OUT, o_sum);
}

// round 16
// speedup vs baseline: 1.1763x; 1.1763x over previous
#include <cuda_runtime.h>
#include <cuda_bf16.h>
#include <cuda_fp16.h>
#include <math.h>
#include <stdint.h>

// ---------------------------------------------------------------------------
// stGCL GAT autoencoder. (base = R14 best, + fp16 gather path)
//  - Feature GEMMs: fp16 mma.sync, fp16 OUTPUT (Hx/Hr stored fp16 only).
//  - Decode hd GEMM: bf16 3-term, fp16 output.
//  - dots + csr_attn gather fp16 (half traffic).
//  - Decode projections: fp16 GEMM, fp32 output (final).
//  - W2 encode GEMM: bf16 3-term, fp32 output (h2 output).
// NOTE: tcgen05 unusable — harness compiles for plain sm_103 target.
// ---------------------------------------------------------------------------

#define MAXN 30016
#define MAXE 480000
#define MAXAK 3000

typedef __nv_bfloat16 bf16;

__device__ bf16  g_Ah[(size_t)MAXN * MAXAK];   // also aliased as __half buffer
__device__ bf16  g_Al[(size_t)MAXN * 512];
__device__ float g_Hx[MAXN * 256];             // aliased: __half Hx16
__device__ float g_Hr[MAXN * 256];             // aliased: __half Hr16
__device__ float g_A [MAXN * 512];             // aliased: __half hd16
__device__ float g_es[MAXN];
__device__ float g_ed[MAXN];
__device__ float g_esx[MAXN];
__device__ float g_edx[MAXN];
__device__ float g_esr[MAXN];
__device__ float g_edr[MAXN];
__device__ int g_roff[MAXN + 1];
__device__ int g_cnt [MAXN];
__device__ int g_cur [MAXN];
__device__ int g_rsrc[MAXE];
// weights
__device__ __half g_W1xT_f16[256 * 3000];   // [NH][INX]
__device__ __half g_W1rT_f16[256 * 2048];   // [NH][INR]
__device__ __half g_W1x_f16 [3000 * 256];   // [INX][NH]
__device__ __half g_W1r_f16 [2048 * 256];   // [INR][NH]
__device__ bf16 g_W2T_h [64 * 512];    __device__ bf16 g_W2T_l [64 * 512];
__device__ bf16 g_W2_h  [512 * 64];    __device__ bf16 g_W2_l  [512 * 64];

// ---------------------------------------------------------------------------
// helpers
// ---------------------------------------------------------------------------
__device__ __forceinline__ uint32_t s2u(const void* p)
{
    return (uint32_t)__cvta_generic_to_shared(p);
}

__device__ __forceinline__ void cpasync16(uint32_t saddr, const void* gaddr, bool pred)
{
    int sz = pred ? 16 : 0;
    asm volatile("cp.async.cg.shared.global [%0], [%1], 16, %2;\n"
                 :: "r"(saddr), "l"(gaddr), "r"(sz));
}

__device__ __forceinline__ void ldmatrix_x4(uint32_t* r, uint32_t saddr)
{
    asm volatile("ldmatrix.sync.aligned.m8n8.x4.shared.b16 {%0,%1,%2,%3}, [%4];"
                 : "=r"(r[0]), "=r"(r[1]), "=r"(r[2]), "=r"(r[3]) : "r"(saddr));
}

__device__ __forceinline__ void ldmatrix_x2(uint32_t* r, uint32_t saddr)
{
    asm volatile("ldmatrix.sync.aligned.m8n8.x2.shared.b16 {%0,%1}, [%2];"
                 : "=r"(r[0]), "=r"(r[1]) : "r"(saddr));
}

__device__ __forceinline__ void mma16816_bf(float* c, const uint32_t* a, const uint32_t* b)
{
    asm volatile("mma.sync.aligned.m16n8k16.row.col.f32.bf16.bf16.f32 "
                 "{%0,%1,%2,%3}, {%4,%5,%6,%7}, {%8,%9}, {%0,%1,%2,%3};"
                 : "+f"(c[0]), "+f"(c[1]), "+f"(c[2]), "+f"(c[3])
                 : "r"(a[0]), "r"(a[1]), "r"(a[2]), "r"(a[3]), "r"(b[0]), "r"(b[1]));
}

__device__ __forceinline__ void mma16816_f16(float* c, const uint32_t* a, const uint32_t* b)
{
    asm volatile("mma.sync.aligned.m16n8k16.row.col.f32.f16.f16.f32 "
                 "{%0,%1,%2,%3}, {%4,%5,%6,%7}, {%8,%9}, {%0,%1,%2,%3};"
                 : "+f"(c[0]), "+f"(c[1]), "+f"(c[2]), "+f"(c[3])
                 : "r"(a[0]), "r"(a[1]), "r"(a[2]), "r"(a[3]), "r"(b[0]), "r"(b[1]));
}

// ---------------------------------------------------------------------------
// conversion kernels
// ---------------------------------------------------------------------------
__global__ void split_kernel(const float* __restrict__ x,
                             bf16* __restrict__ hi, bf16* __restrict__ lo,
                             size_t n)
{
    size_t i = (size_t)blockIdx.x * blockDim.x + threadIdx.x;
    if (i >= n) return;
    float v = x[i];
    bf16 h = __float2bfloat16(v);
    hi[i] = h;
    lo[i] = __float2bfloat16(v - __bfloat162float(h));
}

__global__ void tsplit_kernel(const float* __restrict__ x, int R, int C,
                              bf16* __restrict__ hi, bf16* __restrict__ lo)
{
    int i = blockIdx.x * blockDim.x + threadIdx.x;
    if (i >= R * C) return;
    int c = i / R;
    int r = i - c * R;
    float v = x[(size_t)r * C + c];
    bf16 h = __float2bfloat16(v);
    hi[i] = h;
    lo[i] = __float2bfloat16(v - __bfloat162float(h));
}

// vectorized fp32->fp16 (n divisible by 4; 16B-aligned input)
__global__ void cvt_f16_v4_kernel(const float4* __restrict__ x,
                                  uint2* __restrict__ y, size_t n4)
{
    size_t i = (size_t)blockIdx.x * blockDim.x + threadIdx.x;
    if (i >= n4) return;
    float4 v = x[i];
    __half2 a = __floats2half2_rn(v.x, v.y);
    __half2 b = __floats2half2_rn(v.z, v.w);
    uint2 o;
    o.x = *(const unsigned int*)&a;
    o.y = *(const unsigned int*)&b;
    y[i] = o;
}

// transpose + fp16: out[c][r] = fp16(x[r][c]), out dims [C][R]
__global__ void tcvt_f16_kernel(const float* __restrict__ x, int R, int C,
                                __half* __restrict__ y)
{
    int i = blockIdx.x * blockDim.x + threadIdx.x;
    if (i >= R * C) return;
    int c = i / R;
    int r = i - c * R;
    y[i] = __float2half(x[(size_t)r * C + c]);
}

// ===========================================================================
// 3-term bf16 split GEMM: C[M,N] = (Ah+Al)[M,K]*(Bh+Bl)[N,K]^T
// Output: fp32 (Cf) or fp16 (Ch) — exactly one non-null.
// ===========================================================================
#define BM 128
#define BN 128
#define BKT 32
#define SROW 40
#define TILE_E (BM * SROW)
#define SMEM_BYTES (4 * 2 * TILE_E * 2)

__global__ __launch_bounds__(256) void gemm_mma_kernel(
    const bf16* __restrict__ Ah, const bf16* __restrict__ Al, int lda,
    const bf16* __restrict__ Bh, const bf16* __restrict__ Bl, int ldb,
    float* __restrict__ Cf, __half* __restrict__ Ch, int ldc,
    int M, int N, int K)
{
    extern __shared__ bf16 smem[];
    const int tid  = threadIdx.x;
    const int lane = tid & 31;
    const int wid  = tid >> 5;
    const int wm   = wid & 1;
    const int wn   = wid >> 1;
    const int bm   = blockIdx.y * BM;
    const int bn   = blockIdx.x * BN;

    bf16* sA[2][2]; bf16* sB[2][2];
    #pragma unroll
    for (int st = 0; st < 2; st++) {
        bf16* base = smem + st * 4 * TILE_E;
        sA[st][0] = base;
        sA[st][1] = base + TILE_E;
        sB[st][0] = base + 2 * TILE_E;
        sB[st][1] = base + 3 * TILE_E;
    }

    float acc[4][4][4];
    #pragma unroll
    for (int i = 0; i < 4; i++)
        #pragma unroll
        for (int j = 0; j < 4; j++)
            #pragma unroll
            for (int k = 0; k < 4; k++) acc[i][j][k] = 0.f;

    const int KT = (K + BKT - 1) / BKT;

    auto load_stage = [&](int st, int k0) {
        #pragma unroll
        for (int j = 0; j < 2; j++) {
            int chunk = tid + j * 256;
            int row = chunk >> 2;
            int cc  = chunk & 3;
            int gk  = k0 + cc * 8;
            {
                int gr = bm + row;
                bool p = (gr < M) && (gk < K);
                size_t off = (size_t)(p ? gr : 0) * lda + (p ? gk : 0);
                cpasync16(s2u(sA[st][0] + row * SROW + cc * 8), Ah + off, p);
                cpasync16(s2u(sA[st][1] + row * SROW + cc * 8), Al + off, p);
            }
            {
                int gr = bn + row;
                bool p = (gr < N) && (gk < K);
                size_t off = (size_t)(p ? gr : 0) * ldb + (p ? gk : 0);
                cpasync16(s2u(sB[st][0] + row * SROW + cc * 8), Bh + off, p);
                cpasync16(s2u(sB[st][1] + row * SROW + cc * 8), Bl + off, p);
            }
        }
    };

    load_stage(0, 0);
    asm volatile("cp.async.commit_group;\n");

    for (int kt = 0; kt < KT; kt++) {
        if (kt + 1 < KT) {
            load_stage((kt + 1) & 1, (kt + 1) * BKT);
            asm volatile("cp.async.commit_group;\n");
            asm volatile("cp.async.wait_group 1;\n");
        } else {
            asm volatile("cp.async.wait_group 0;\n");
        }
        __syncthreads();

        int st = kt & 1;
        #pragma unroll
        for (int kk = 0; kk < BKT; kk += 16) {
            uint32_t ah[4][4], al[4][4];
            int arow = wm * 64 + (lane & 15);
            int acol = kk + (lane >> 4) * 8;
            #pragma unroll
            for (int mi = 0; mi < 4; mi++) {
                ldmatrix_x4(ah[mi], s2u(sA[st][0] + (arow + mi * 16) * SROW + acol));
                ldmatrix_x4(al[mi], s2u(sA[st][1] + (arow + mi * 16) * SROW + acol));
            }
            int brow = wn * 32 + (lane & 7);
            int bcol = kk + ((lane >> 3) & 1) * 8;
            uint32_t bb[4][2];
            #pragma unroll
            for (int ni = 0; ni < 4; ni++)
                ldmatrix_x2(bb[ni], s2u(sB[st][0] + (brow + ni * 8) * SROW + bcol));
            #pragma unroll
            for (int mi = 0; mi < 4; mi++)
                #pragma unroll
                for (int ni = 0; ni < 4; ni++) {
                    mma16816_bf(acc[mi][ni], ah[mi], bb[ni]);
                    mma16816_bf(acc[mi][ni], al[mi], bb[ni]);
                }
            #pragma unroll
            for (int ni = 0; ni < 4; ni++)
                ldmatrix_x2(bb[ni], s2u(sB[st][1] + (brow + ni * 8) * SROW + bcol));
            #pragma unroll
            for (int mi = 0; mi < 4; mi++)
                #pragma unroll
                for (int ni = 0; ni < 4; ni++)
                    mma16816_bf(acc[mi][ni], ah[mi], bb[ni]);
        }
        __syncthreads();
    }

    const int group = lane >> 2;
    const int tig   = lane & 3;
    #pragma unroll
    for (int mi = 0; mi < 4; mi++) {
        #pragma unroll
        for (int ni = 0; ni < 4; ni++) {
            int col = bn + wn * 32 + ni * 8 + tig * 2;
            if (col >= N) continue;
            int r0 = bm + wm * 64 + mi * 16 + group;
            int r1 = r0 + 8;
            if (Ch) {
                if (r0 < M)
                    *(__half2*)&Ch[(size_t)r0 * ldc + col] =
                        __floats2half2_rn(acc[mi][ni][0], acc[mi][ni][1]);
                if (r1 < M)
                    *(__half2*)&Ch[(size_t)r1 * ldc + col] =
                        __floats2half2_rn(acc[mi][ni][2], acc[mi][ni][3]);
            } else {
                if (r0 < M) {
                    float2 v = make_float2(acc[mi][ni][0], acc[mi][ni][1]);
                    *(float2*)&Cf[(size_t)r0 * ldc + col] = v;
                }
                if (r1 < M) {
                    float2 v = make_float2(acc[mi][ni][2], acc[mi][ni][3]);
                    *(float2*)&Cf[(size_t)r1 * ldc + col] = v;
                }
            }
        }
    }
}

// ===========================================================================
// single-term fp16 GEMM (2-stage, proven): C[M,N] = A[M,K]*B[N,K]^T
// Output: fp32 (Cf) or fp16 (Ch) — exactly one non-null.
// ===========================================================================
#define SMEM_F16 (2 * 2 * TILE_E * 2)   // 40960 B

__global__ __launch_bounds__(256) void gemm_f16_kernel(
    const __half* __restrict__ A, int lda,
    const __half* __restrict__ B, int ldb,
    float* __restrict__ Cf, __half* __restrict__ Ch, int ldc,
    int M, int N, int K)
{
    extern __shared__ __half smh[];
    const int tid  = threadIdx.x;
    const int lane = tid & 31;
    const int wid  = tid >> 5;
    const int wm   = wid & 1;
    const int wn   = wid >> 1;
    const int bm   = blockIdx.y * BM;
    const int bn   = blockIdx.x * BN;

    __half* sA[2]; __half* sB[2];
    #pragma unroll
    for (int st = 0; st < 2; st++) {
        __half* base = smh + st * 2 * TILE_E;
        sA[st] = base;
        sB[st] = base + TILE_E;
    }

    float acc[4][4][4];
    #pragma unroll
    for (int i = 0; i < 4; i++)
        #pragma unroll
        for (int j = 0; j < 4; j++)
            #pragma unroll
            for (int k = 0; k < 4; k++) acc[i][j][k] = 0.f;

    const int KT = (K + BKT - 1) / BKT;

    auto load_stage = [&](int st, int k0) {
        #pragma unroll
        for (int j = 0; j < 2; j++) {
            int chunk = tid + j * 256;
            int row = chunk >> 2;
            int cc  = chunk & 3;
            int gk  = k0 + cc * 8;
            {
                int gr = bm + row;
                bool p = (gr < M) && (gk < K);
                size_t off = (size_t)(p ? gr : 0) * lda + (p ? gk : 0);
                cpasync16(s2u(sA[st] + row * SROW + cc * 8), A + off, p);
            }
            {
                int gr = bn + row;
                bool p = (gr < N) && (gk < K);
                size_t off = (size_t)(p ? gr : 0) * ldb + (p ? gk : 0);
                cpasync16(s2u(sB[st] + row * SROW + cc * 8), B + off, p);
            }
        }
    };

    load_stage(0, 0);
    asm volatile("cp.async.commit_group;\n");

    for (int kt = 0; kt < KT; kt++) {
        if (kt + 1 < KT) {
            load_stage((kt + 1) & 1, (kt + 1) * BKT);
            asm volatile("cp.async.commit_group;\n");
            asm volatile("cp.async.wait_group 1;\n");
        } else {
            asm volatile("cp.async.wait_group 0;\n");
        }
        __syncthreads();

        int st = kt & 1;
        #pragma unroll
        for (int kk = 0; kk < BKT; kk += 16) {
            uint32_t af[4][4];
            int arow = wm * 64 + (lane & 15);
            int acol = kk + (lane >> 4) * 8;
            #pragma unroll
            for (int mi = 0; mi < 4; mi++)
                ldmatrix_x4(af[mi], s2u(sA[st] + (arow + mi * 16) * SROW + acol));
            int brow = wn * 32 + (lane & 7);
            int bcol = kk + ((lane >> 3) & 1) * 8;
            uint32_t bb[4][2];
            #pragma unroll
            for (int ni = 0; ni < 4; ni++)
                ldmatrix_x2(bb[ni], s2u(sB[st] + (brow + ni * 8) * SROW + bcol));
            #pragma unroll
            for (int mi = 0; mi < 4; mi++)
                #pragma unroll
                for (int ni = 0; ni < 4; ni++)
                    mma16816_f16(acc[mi][ni], af[mi], bb[ni]);
        }
        __syncthreads();
    }

    const int group = lane >> 2;
    const int tig   = lane & 3;
    #pragma unroll
    for (int mi = 0; mi < 4; mi++) {
        #pragma unroll
        for (int ni = 0; ni < 4; ni++) {
            int col = bn + wn * 32 + ni * 8 + tig * 2;
            if (col >= N) continue;
            int r0 = bm + wm * 64 + mi * 16 + group;
            int r1 = r0 + 8;
            if (Ch) {
                if (r0 < M)
                    *(__half2*)&Ch[(size_t)r0 * ldc + col] =
                        __floats2half2_rn(acc[mi][ni][0], acc[mi][ni][1]);
                if (r1 < M)
                    *(__half2*)&Ch[(size_t)r1 * ldc + col] =
                        __floats2half2_rn(acc[mi][ni][2], acc[mi][ni][3]);
            } else {
                if (r0 < M) {
                    float2 v = make_float2(acc[mi][ni][0], acc[mi][ni][1]);
                    *(float2*)&Cf[(size_t)r0 * ldc + col] = v;
                }
                if (r1 < M) {
                    float2 v = make_float2(acc[mi][ni][2], acc[mi][ni][3]);
                    *(float2*)&Cf[(size_t)r1 * ldc + col] = v;
                }
            }
        }
    }
}

// ---------------------------------------------------------------------------
// CSR build
// ---------------------------------------------------------------------------
__global__ void zero_cnt_kernel(int* cnt, int N)
{
    int i = blockIdx.x * blockDim.x + threadIdx.x;
    if (i < N) cnt[i] = 0;
}

__global__ void count_kernel(const int* __restrict__ dst, int* cnt, int E)
{
    int i = blockIdx.x * blockDim.x + threadIdx.x;
    if (i < E) atomicAdd(&cnt[dst[i]], 1);
}

__global__ void scan_kernel(const int* __restrict__ cnt,
                            int* __restrict__ roff, int* __restrict__ cur, int N)
{
    __shared__ int ssum[1024];
    int t = threadIdx.x;
    int per = (N + 1023) / 1024;
    int b = t * per;
    int loc = 0;
    for (int i = 0; i < per; i++)
        if (b + i < N) loc += cnt[b + i];
    ssum[t] = loc;
    __syncthreads();
    for (int o = 1; o < 1024; o <<= 1) {
        int v = (t >= o) ? ssum[t - o] : 0;
        __syncthreads();
        ssum[t] += v;
        __syncthreads();
    }
    int run = (t == 0) ? 0 : ssum[t - 1];
    for (int i = 0; i < per; i++) {
        if (b + i < N) {
            roff[b + i] = run;
            cur[b + i]  = run;
            run += cnt[b + i];
        }
    }
    if (t == 1023) roff[N] = ssum[1023];
}

__global__ void fill_kernel(const int* __restrict__ src,
                            const int* __restrict__ dst,
                            int* __restrict__ cur, int* __restrict__ rsrc, int E)
{
    int i = blockIdx.x * blockDim.x + threadIdx.x;
    if (i >= E) return;
    int pos = atomicAdd(&cur[dst[i]], 1);
    rsrc[pos] = src[i];
}

// ---------------------------------------------------------------------------
// Attention (fp16 H)
// ---------------------------------------------------------------------------
__global__ void dots_kernel(const __half* __restrict__ H, int ld, int D,
                            const float* __restrict__ asrc,
                            const float* __restrict__ adst,
                            float* __restrict__ es, float* __restrict__ ed, int N)
{
    int warp = (blockIdx.x * blockDim.x + threadIdx.x) >> 5;
    int lane = threadIdx.x & 31;
    if (warp >= N) return;
    const __half* h = H + (size_t)warp * ld;
    float s1 = 0.f, s2 = 0.f;
    for (int d = lane; d < D; d += 32) {
        float v = __half2float(h[d]);
        s1 += v * asrc[d];
        s2 += v * adst[d];
    }
    #pragma unroll
    for (int o = 16; o; o >>= 1) {
        s1 += __shfl_xor_sync(0xffffffffu, s1, o);
        s2 += __shfl_xor_sync(0xffffffffu, s2, o);
    }
    if (lane == 0) { es[warp] = s1; ed[warp] = s2; }
}

// Fused per-node softmax + aggregation + ELU + output convert.
// H is fp16 (half gather traffic). Aggregation loop = R14's proven form.
// OMODE: 0 = bf16 hi/lo split pair, 1 = single fp16.
#define ACHUNK 64
template <int NCH, int OMODE>
__global__ __launch_bounds__(256) void csr_attn_kernel(
    const __half* __restrict__ H, int ldh,
    const int* __restrict__ p,
    const float* __restrict__ es, const float* __restrict__ ed,
    const int* __restrict__ roff, const int* __restrict__ rsrc,
    bf16* __restrict__ outh, bf16* __restrict__ outl,
    int ldo, int coloff)
{
    const int node = blockIdx.x;
    const int tid  = threadIdx.x;
    const int lane = tid & 31;
    const int wid  = tid >> 5;
    const int beg = roff[node];
    const int deg = roff[node + 1] - beg;

    __shared__ float s_w[ACHUNK];
    __shared__ int   s_src[ACHUNK];
    __shared__ float s_ms[2];

    const float edv = ed[p ? p[node] : node];

    if (wid == 0) {
        float m = -INFINITY;
        for (int j = lane; j < deg; j += 32) {
            int sidx = rsrc[beg + j];
            float e = es[p ? p[sidx] : sidx] + edv;
            e = (e >= 0.f) ? e : 0.2f * e;
            m = fmaxf(m, e);
        }
        #pragma unroll
        for (int o = 16; o; o >>= 1) m = fmaxf(m, __shfl_xor_sync(0xffffffffu, m, o));
        float ssum = 0.f;
        for (int j = lane; j < deg; j += 32) {
            int sidx = rsrc[beg + j];
            float e = es[p ? p[sidx] : sidx] + edv;
            e = (e >= 0.f) ? e : 0.2f * e;
            ssum += __expf(e - m);
        }
        #pragma unroll
        for (int o = 16; o; o >>= 1) ssum += __shfl_xor_sync(0xffffffffu, ssum, o);
        if (lane == 0) { s_ms[0] = m; s_ms[1] = ssum; }
    }
    __syncthreads();
    const float m    = s_ms[0];
    const float invs = 1.f / (s_ms[1] + 1e-16f);

    float acc0 = 0.f, acc1 = 0.f;
    for (int c0 = 0; c0 < deg; c0 += ACHUNK) {
        int cl = min(ACHUNK, deg - c0);
        if (tid < cl) {
            int sidx = rsrc[beg + c0 + tid];
            int ps = p ? p[sidx] : sidx;
            float e = es[ps] + edv;
            e = (e >= 0.f) ? e : 0.2f * e;
            s_w[tid]   = __expf(e - m) * invs;
            s_src[tid] = ps;
        }
        __syncthreads();
        for (int j = 0; j < cl; j++) {
            const __half* hrow = H + (size_t)s_src[j] * ldh;
            float w = s_w[j];
            acc0 += w * __half2float(hrow[tid]);
            if (NCH == 2) acc1 += w * __half2float(hrow[tid + 256]);
        }
        __syncthreads();
    }

    acc0 = (acc0 > 0.f) ? acc0 : expm1f(acc0);
    if (NCH == 2) acc1 = (acc1 > 0.f) ? acc1 : expm1f(acc1);

    size_t base = (size_t)node * ldo + coloff;
    if (OMODE == 0) {
        bf16 h0 = __float2bfloat16(acc0);
        outh[base + tid] = h0;
        outl[base + tid] = __float2bfloat16(acc0 - __bfloat162float(h0));
        if (NCH == 2) {
            bf16 h1 = __float2bfloat16(acc1);
            outh[base + tid + 256] = h1;
            outl[base + tid + 256] = __float2bfloat16(acc1 - __bfloat162float(h1));
        }
    } else {
        __half* oh = (__half*)outh;
        oh[base + tid] = __float2half(acc0);
        if (NCH == 2) oh[base + tid + 256] = __float2half(acc1);
    }
}

__global__ void summary_kernel(const float* __restrict__ h2, int N, int C,
                               float* __restrict__ out)
{
    int c = blockIdx.x;
    float acc = 0.f;
    for (int r = threadIdx.x; r < N; r += blockDim.x)
        acc += h2[(size_t)r * C + c];
    __shared__ float sh[256];
    sh[threadIdx.x] = acc;
    __syncthreads();
    for (int o = 128; o; o >>= 1) {
        if (threadIdx.x < o) sh[threadIdx.x] += sh[threadIdx.x + o];
        __syncthreads();
    }
    if (threadIdx.x == 0)
        out[c] = 1.f / (1.f + expf(-sh[0] / (float)N));
}

// ---------------------------------------------------------------------------
// Host side
// ---------------------------------------------------------------------------
static void gemm_mma(const bf16* Ah, const bf16* Al, int lda,
                     const bf16* Bh, const bf16* Bl, int ldb,
                     float* Cf, __half* Ch, int ldc, int M, int N, int K)
{
    dim3 grid((N + BN - 1) / BN, (M + BM - 1) / BM);
    gemm_mma_kernel<<<grid, 256, SMEM_BYTES>>>(Ah, Al, lda, Bh, Bl, ldb,
                                               Cf, Ch, ldc, M, N, K);
}

static void gemm_f16(const __half* A, int lda, const __half* B, int ldb,
                     float* Cf, __half* Ch, int ldc, int M, int N, int K)
{
    dim3 grid((N + BN - 1) / BN, (M + BM - 1) / BM);
    gemm_f16_kernel<<<grid, 256, SMEM_F16>>>(A, lda, B, ldb, Cf, Ch, ldc, M, N, K);
}

static void split(const float* x, bf16* hi, bf16* lo, size_t n)
{
    split_kernel<<<(unsigned)((n + 255) / 256), 256>>>(x, hi, lo, n);
}

static void cvt_f16(const float* x, __half* y, size_t n)  // n % 4 == 0
{
    size_t n4 = n / 4;
    cvt_f16_v4_kernel<<<(unsigned)((n4 + 255) / 256), 256>>>(
        (const float4*)x, (uint2*)y, n4);
}

extern "C" void kernel_launch(void* const* d_in, const int* in_sizes, int n_in,
                              void* d_out, int out_size)
{
    const float* features = (const float*)d_in[0];
    const float* imf      = (const float*)d_in[1];
    const float* W1x      = (const float*)d_in[2];
    const float* a1x_src  = (const float*)d_in[3];
    const float* a1x_dst  = (const float*)d_in[4];
    const float* W1r      = (const float*)d_in[5];
    const float* a1r_src  = (const float*)d_in[6];
    const float* a1r_dst  = (const float*)d_in[7];
    const float* W2       = (const float*)d_in[8];
    const float* a3_src   = (const float*)d_in[9];
    const float* a3_dst   = (const float*)d_in[10];
    const int*   edge     = (const int*)d_in[11];
    const int*   perm     = (const int*)d_in[12];

    const int NH  = in_sizes[3];              // 256
    const int INX = in_sizes[2] / NH;         // 3000
    const int INR = in_sizes[5] / NH;         // 2048
    const int OUT = in_sizes[8] / (2 * NH);   // 64
    const int N   = in_sizes[0] / INX;        // 30000
    const int E   = in_sizes[11] / 2;         // 480000
    const int D2  = 2 * NH;                   // 512

    const int* src = edge;
    const int* dst = edge + E;

    cudaFuncSetAttribute(gemm_mma_kernel,
                         cudaFuncAttributeMaxDynamicSharedMemorySize, SMEM_BYTES);
    cudaFuncSetAttribute(gemm_f16_kernel,
                         cudaFuncAttributeMaxDynamicSharedMemorySize, SMEM_F16);

    bf16 *Ah, *Al;
    __half *W1xT_f16, *W1rT_f16, *W1x_f16, *W1r_f16;
    bf16 *W2T_h, *W2T_l, *W2_h, *W2_l;
    float *HxBuf, *HrBuf, *Abuf, *es, *ed, *esx, *edx, *esr, *edr;
    int *roff, *cnt, *cur, *rsrc;
    cudaGetSymbolAddress((void**)&Ah,    g_Ah);
    cudaGetSymbolAddress((void**)&Al,    g_Al);
    cudaGetSymbolAddress((void**)&HxBuf, g_Hx);
    cudaGetSymbolAddress((void**)&HrBuf, g_Hr);
    cudaGetSymbolAddress((void**)&Abuf,  g_A);
    cudaGetSymbolAddress((void**)&es,    g_es);
    cudaGetSymbolAddress((void**)&ed,    g_ed);
    cudaGetSymbolAddress((void**)&esx,   g_esx);
    cudaGetSymbolAddress((void**)&edx,   g_edx);
    cudaGetSymbolAddress((void**)&esr,   g_esr);
    cudaGetSymbolAddress((void**)&edr,   g_edr);
    cudaGetSymbolAddress((void**)&roff,  g_roff);
    cudaGetSymbolAddress((void**)&cnt,   g_cnt);
    cudaGetSymbolAddress((void**)&cur,   g_cur);
    cudaGetSymbolAddress((void**)&rsrc,  g_rsrc);
    cudaGetSymbolAddress((void**)&W1xT_f16, g_W1xT_f16);
    cudaGetSymbolAddress((void**)&W1rT_f16, g_W1rT_f16);
    cudaGetSymbolAddress((void**)&W1x_f16,  g_W1x_f16);
    cudaGetSymbolAddress((void**)&W1r_f16,  g_W1r_f16);
    cudaGetSymbolAddress((void**)&W2T_h,  g_W2T_h);
    cudaGetSymbolAddress((void**)&W2T_l,  g_W2T_l);
    cudaGetSymbolAddress((void**)&W2_h,   g_W2_h);
    cudaGetSymbolAddress((void**)&W2_l,   g_W2_l);

    __half* Hx16 = (__half*)HxBuf;   // N x NH fp16
    __half* Hr16 = (__half*)HrBuf;   // N x NH fp16
    __half* hd16 = (__half*)Abuf;    // N x D2 fp16

    float* out = (float*)d_out;
    float* o_h2   = out;
    float* o_h4x  = o_h2   + (size_t)N * OUT;
    float* o_h4r  = o_h4x  + (size_t)N * INX;
    float* o_rh2  = o_h4r  + (size_t)N * INR;
    float* o_rh4x = o_rh2  + (size_t)N * OUT;
    float* o_rh4r = o_rh4x + (size_t)N * INX;
    float* o_sum  = o_rh4r + (size_t)N * INR;

    // ---- CSR build ----
    zero_cnt_kernel<<<(N + 255) / 256, 256>>>(cnt, N);
    count_kernel<<<(E + 255) / 256, 256>>>(dst, cnt, E);
    scan_kernel<<<1, 1024>>>(cnt, roff, cur, N);
    fill_kernel<<<(E + 255) / 256, 256>>>(src, dst, cur, rsrc, E);

    // ---- weight preps ----
    tcvt_f16_kernel<<<(INX * NH + 255) / 256, 256>>>(W1x, INX, NH, W1xT_f16);
    tcvt_f16_kernel<<<(INR * NH + 255) / 256, 256>>>(W1r, INR, NH, W1rT_f16);
    tsplit_kernel<<<(D2 * OUT + 255) / 256, 256>>>(W2, D2, OUT, W2T_h, W2T_l);
    split(W2, W2_h, W2_l, (size_t)D2 * OUT);
    cvt_f16(W1x, W1x_f16, (size_t)INX * NH);
    cvt_f16(W1r, W1r_f16, (size_t)INR * NH);

    // ---- shared pre-attention features: fp16 GEMM, fp16 output ----
    __half* Af16 = (__half*)Ah;
    cvt_f16(features, Af16, (size_t)N * INX);
    gemm_f16(Af16, INX, W1xT_f16, INX, nullptr, Hx16, NH, N, NH, INX);
    cvt_f16(imf, Af16, (size_t)N * INR);
    gemm_f16(Af16, INR, W1rT_f16, INR, nullptr, Hr16, NH, N, NH, INR);

    // ---- encode dots once (perm path uses gather identity) ----
    dots_kernel<<<(N + 7) / 8, 256>>>(Hx16, NH, NH, a1x_src, a1x_dst, esx, edx, N);
    dots_kernel<<<(N + 7) / 8, 256>>>(Hr16, NH, NH, a1r_src, a1r_dst, esr, edr, N);

    for (int path = 0; path < 2; path++) {
        const int* p = path ? perm : nullptr;
        float* oh2  = path ? o_rh2  : o_h2;
        float* oh4x = path ? o_rh4x : o_h4x;
        float* oh4r = path ? o_rh4r : o_h4r;

        // --- encode: GAT layers (bf16 split out) -> @W2 (3-term, fp32 out) ---
        csr_attn_kernel<1, 0><<<N, 256>>>(Hx16, NH, p, esx, edx, roff, rsrc,
                                          Ah, Al, D2, 0);
        csr_attn_kernel<1, 0><<<N, 256>>>(Hr16, NH, p, esr, edr, roff, rsrc,
                                          Ah, Al, D2, NH);
        gemm_mma(Ah, Al, D2, W2T_h, W2T_l, D2, oh2, nullptr, OUT, N, OUT, D2);

        // --- decode: hd = h2 @ W2^T (3-term, fp16 out), GAT (fp16), project ---
        split(oh2, Ah, Al, (size_t)N * OUT);
        gemm_mma(Ah, Al, OUT, W2_h, W2_l, OUT, nullptr, hd16, D2, N, D2, OUT);

        dots_kernel<<<(N + 7) / 8, 256>>>(hd16, D2, D2, a3_src, a3_dst, es, ed, N);
        csr_attn_kernel<2, 1><<<N, 256>>>(hd16, D2, nullptr, es, ed, roff, rsrc,
                                          Ah, nullptr, D2, 0);

        const __half* H3 = (const __half*)Ah;
        gemm_f16(H3,      D2, W1x_f16, NH, oh4x, nullptr, INX, N, INX, NH);
        gemm_f16(H3 + NH, D2, W1r_f16, NH, oh4r, nullptr, INR, N, INR, NH);
    }

    summary_kernel<<<OUT, 256>>>(o_h2, N, OUT, o_sum);
}